// round 1
// baseline (speedup 1.0000x reference)
#include <cuda_runtime.h>
#include <math.h>
#include <stddef.h>

// Problem constants
#define B_  2
#define S_  2048
#define D_  1024
#define H_  16
#define FK_ 32
#define DK_ 64
#define BH_ (B_*H_)

// ---------------- scratch (__device__ globals; no allocation allowed) ----------------
__device__ float g_M[H_*DK_*DK_];                 // per-head collapsed 64x64 projection
__device__ float g_Qp[B_*S_*D_];                  // [B,S,D] layout (h*64+d)
__device__ float g_vp[B_*S_*D_];                  // v@Wv+bv, [B,S,D]
__device__ float g_concat[B_*S_*D_];              // attention output pre-Wo
__device__ float g_scores[134217728];             // [B*H, S, S] = 512 MB

// ---------------- 1) collapse the low-rank chain per head, in fp64 ----------------
// M[h] = Wa[h] @ Wb[h] @ Wa2[h] @ Wb2[h]
// Wa[h][c][j]  = W_A [h*2048 + c*32 + j]
// Wb[h][j][d]  = W_A [h*2048 + j*64 + d]   (same data, different view)
// Wa2/Wb2 same from W_A2.
__global__ void compute_M_kernel(const float* __restrict__ W_A,
                                 const float* __restrict__ W_A2) {
    int h = blockIdx.x;
    __shared__ double T1[64*64];   // Wa@Wb
    __shared__ double T2[64*32];   // T1@Wa2
    const float* WAh  = W_A  + h*2048;
    const float* WA2h = W_A2 + h*2048;

    for (int idx = threadIdx.x; idx < 4096; idx += blockDim.x) {
        int c = idx >> 6, d = idx & 63;
        double acc = 0.0;
        #pragma unroll 8
        for (int j = 0; j < 32; j++)
            acc += (double)WAh[c*32 + j] * (double)WAh[j*64 + d];
        T1[idx] = acc;
    }
    __syncthreads();
    for (int idx = threadIdx.x; idx < 2048; idx += blockDim.x) {
        int c = idx >> 5, j = idx & 31;
        double acc = 0.0;
        #pragma unroll 8
        for (int d = 0; d < 64; d++)
            acc += T1[c*64 + d] * (double)WA2h[d*32 + j];
        T2[idx] = acc;
    }
    __syncthreads();
    for (int idx = threadIdx.x; idx < 4096; idx += blockDim.x) {
        int c = idx >> 6, d = idx & 63;
        double acc = 0.0;
        #pragma unroll 8
        for (int j = 0; j < 32; j++)
            acc += T2[c*32 + j] * (double)WA2h[j*64 + d];
        g_M[h*4096 + idx] = (float)acc;
    }
}

// ---------------- 2) Qp = q @ M[h] per head ----------------
// one block per token (b*S+s), 256 threads: thread handles d = tid&63, heads tid>>6 + 4*hh
__global__ void qp_kernel(const float* __restrict__ q) {
    int token = blockIdx.x;
    __shared__ float qs[D_];
    const float* qrow = q + (size_t)token * D_;
    for (int i = threadIdx.x; i < D_; i += 256) qs[i] = qrow[i];
    __syncthreads();
    int d  = threadIdx.x & 63;
    int h0 = threadIdx.x >> 6;          // 0..3
    float* out = g_Qp + (size_t)token * D_;
    #pragma unroll
    for (int hh = 0; hh < 4; hh++) {
        int h = h0 * 4 + hh;
        const float* Mh = g_M + h*4096;
        const float* qh = qs + h*64;
        float acc = 0.f;
        #pragma unroll 8
        for (int c = 0; c < 64; c++) acc = fmaf(qh[c], Mh[c*64 + d], acc);
        out[h*64 + d] = acc;
    }
}

// ---------------- 3) generic SGEMM (row-major A[M,K] * B[K,N] + bias) ----------------
// 128x128 tile, BK=16, 256 threads, 8x8 micro-tile. Shapes assumed divisible.
__global__ __launch_bounds__(256)
void sgemm_nn_bias(int M, int N, int K,
                   const float* __restrict__ A,
                   const float* __restrict__ Bm,
                   const float* __restrict__ bias,
                   float* __restrict__ C) {
    __shared__ float As[16][128];
    __shared__ float Bs[16][128];
    int bm = blockIdx.y * 128;
    int bn = blockIdx.x * 128;
    int tid = threadIdx.x;
    int tx = tid & 15, ty = tid >> 4;

    float acc[8][8];
    #pragma unroll
    for (int i = 0; i < 8; i++)
        #pragma unroll
        for (int j = 0; j < 8; j++) acc[i][j] = 0.f;

    int arow = tid >> 1;          // 0..127
    int acol = (tid & 1) * 8;     // 0 or 8
    int brow = tid >> 4;          // 0..15
    int bcol = (tid & 15) * 8;    // 0..120

    for (int k0 = 0; k0 < K; k0 += 16) {
        const float* Ap = A + (size_t)(bm + arow) * K + k0 + acol;
        float4 a0 = *(const float4*)Ap;
        float4 a1 = *(const float4*)(Ap + 4);
        As[acol+0][arow] = a0.x; As[acol+1][arow] = a0.y;
        As[acol+2][arow] = a0.z; As[acol+3][arow] = a0.w;
        As[acol+4][arow] = a1.x; As[acol+5][arow] = a1.y;
        As[acol+6][arow] = a1.z; As[acol+7][arow] = a1.w;

        const float* Bp = Bm + (size_t)(k0 + brow) * N + bn + bcol;
        *(float4*)&Bs[brow][bcol]     = *(const float4*)Bp;
        *(float4*)&Bs[brow][bcol + 4] = *(const float4*)(Bp + 4);
        __syncthreads();

        #pragma unroll
        for (int kk = 0; kk < 16; kk++) {
            float a[8], b[8];
            *(float4*)(a)     = *(float4*)&As[kk][ty*8];
            *(float4*)(a + 4) = *(float4*)&As[kk][ty*8 + 4];
            *(float4*)(b)     = *(float4*)&Bs[kk][tx*8];
            *(float4*)(b + 4) = *(float4*)&Bs[kk][tx*8 + 4];
            #pragma unroll
            for (int i = 0; i < 8; i++)
                #pragma unroll
                for (int j = 0; j < 8; j++)
                    acc[i][j] = fmaf(a[i], b[j], acc[i][j]);
        }
        __syncthreads();
    }

    #pragma unroll
    for (int i = 0; i < 8; i++) {
        int row = bm + ty*8 + i;
        float* Cp = C + (size_t)row * N + bn + tx*8;
        float o[8];
        #pragma unroll
        for (int j = 0; j < 8; j++)
            o[j] = acc[i][j] + bias[bn + tx*8 + j];
        *(float4*)(Cp)     = *(float4*)(o);
        *(float4*)(Cp + 4) = *(float4*)(o + 4);
    }
}

// ---------------- 4) batched NT GEMM: scores[bh][s][t] = Qp[b,s,h,:] . q[b,t,h,:] ----
// K = 64. grid (S/128, S/128, B*H)
__global__ __launch_bounds__(256)
void scores_kernel(const float* __restrict__ q) {
    int bh = blockIdx.z;
    int b = bh >> 4, h = bh & 15;
    const float* A  = g_Qp + (size_t)b * S_ * D_ + h * 64;   // row stride D_
    const float* Bt = q    + (size_t)b * S_ * D_ + h * 64;   // row stride D_
    float* C = g_scores + (size_t)bh * S_ * S_;

    __shared__ float As[16][128];
    __shared__ float Bs[16][128];
    int bm = blockIdx.y * 128;
    int bn = blockIdx.x * 128;
    int tid = threadIdx.x;
    int tx = tid & 15, ty = tid >> 4;

    float acc[8][8];
    #pragma unroll
    for (int i = 0; i < 8; i++)
        #pragma unroll
        for (int j = 0; j < 8; j++) acc[i][j] = 0.f;

    int arow = tid >> 1;
    int acol = (tid & 1) * 8;

    for (int k0 = 0; k0 < 64; k0 += 16) {
        const float* Ap = A + (size_t)(bm + arow) * D_ + k0 + acol;
        float4 a0 = *(const float4*)Ap;
        float4 a1 = *(const float4*)(Ap + 4);
        As[acol+0][arow] = a0.x; As[acol+1][arow] = a0.y;
        As[acol+2][arow] = a0.z; As[acol+3][arow] = a0.w;
        As[acol+4][arow] = a1.x; As[acol+5][arow] = a1.y;
        As[acol+6][arow] = a1.z; As[acol+7][arow] = a1.w;

        const float* Bp = Bt + (size_t)(bn + arow) * D_ + k0 + acol;
        float4 b0 = *(const float4*)Bp;
        float4 b1 = *(const float4*)(Bp + 4);
        Bs[acol+0][arow] = b0.x; Bs[acol+1][arow] = b0.y;
        Bs[acol+2][arow] = b0.z; Bs[acol+3][arow] = b0.w;
        Bs[acol+4][arow] = b1.x; Bs[acol+5][arow] = b1.y;
        Bs[acol+6][arow] = b1.z; Bs[acol+7][arow] = b1.w;
        __syncthreads();

        #pragma unroll
        for (int kk = 0; kk < 16; kk++) {
            float a[8], bb[8];
            *(float4*)(a)      = *(float4*)&As[kk][ty*8];
            *(float4*)(a + 4)  = *(float4*)&As[kk][ty*8 + 4];
            *(float4*)(bb)     = *(float4*)&Bs[kk][tx*8];
            *(float4*)(bb + 4) = *(float4*)&Bs[kk][tx*8 + 4];
            #pragma unroll
            for (int i = 0; i < 8; i++)
                #pragma unroll
                for (int j = 0; j < 8; j++)
                    acc[i][j] = fmaf(a[i], bb[j], acc[i][j]);
        }
        __syncthreads();
    }

    #pragma unroll
    for (int i = 0; i < 8; i++) {
        int row = bm + ty*8 + i;
        float* Cp = C + (size_t)row * S_ + bn + tx*8;
        *(float4*)(Cp)     = *(float4*)(&acc[i][0]);
        *(float4*)(Cp + 4) = *(float4*)(&acc[i][4]);
    }
}

// ---------------- 5) softmax + sparse PV gather (deterministic) ----------------
// scores are ~1e5 scale -> softmax is (near) one-hot. exp(x) == 0 exactly for
// x < -104 in fp32 (reference underflows identically), so only terms with
// s > max-104 contribute. Compact them in t-order via prefix scan (no atomics).
__global__ __launch_bounds__(256)
void softmax_pv_kernel() {
    int s  = blockIdx.x;
    int bh = blockIdx.y;
    int b = bh >> 4, h = bh & 15;
    const float* row = g_scores + ((size_t)bh * S_ + s) * S_;

    __shared__ float red[256];
    __shared__ int   scnt[256];
    __shared__ int   tlist[S_];
    __shared__ float wlist[S_];

    int tid = threadIdx.x;
    // thread owns contiguous t chunk [tid*8, tid*8+8)
    float v8[8];
    {
        const float4* rp = (const float4*)(row + tid * 8);
        float4 r0 = rp[0], r1 = rp[1];
        v8[0]=r0.x; v8[1]=r0.y; v8[2]=r0.z; v8[3]=r0.w;
        v8[4]=r1.x; v8[5]=r1.y; v8[6]=r1.z; v8[7]=r1.w;
    }
    float m = v8[0];
    #pragma unroll
    for (int i = 1; i < 8; i++) m = fmaxf(m, v8[i]);
    red[tid] = m; __syncthreads();
    for (int off = 128; off > 0; off >>= 1) {
        if (tid < off) red[tid] = fmaxf(red[tid], red[tid + off]);
        __syncthreads();
    }
    m = red[0];
    __syncthreads();

    // count actives
    int c = 0;
    #pragma unroll
    for (int i = 0; i < 8; i++) c += (v8[i] - m > -104.0f) ? 1 : 0;

    // inclusive prefix scan (Hillis-Steele, deterministic)
    scnt[tid] = c; __syncthreads();
    for (int off = 1; off < 256; off <<= 1) {
        int x = scnt[tid];
        int y = (tid >= off) ? scnt[tid - off] : 0;
        __syncthreads();
        scnt[tid] = x + y;
        __syncthreads();
    }
    int L = scnt[255];
    int p = scnt[tid] - c;
    #pragma unroll
    for (int i = 0; i < 8; i++) {
        float dsc = v8[i] - m;
        if (dsc > -104.0f) {
            tlist[p] = tid * 8 + i;
            wlist[p] = expf(dsc);
            p++;
        }
    }
    __syncthreads();

    // denominator (deterministic tree)
    float dsum = 0.f;
    for (int i = tid; i < L; i += 256) dsum += wlist[i];
    red[tid] = dsum; __syncthreads();
    for (int off = 128; off > 0; off >>= 1) {
        if (tid < off) red[tid] += red[tid + off];
        __syncthreads();
    }
    float denom = red[0];

    // weighted gather of vp rows (L is typically 1-4)
    if (tid < 64) {
        float o = 0.f;
        const float* vpb = g_vp + (size_t)b * S_ * D_ + h * 64 + tid;
        for (int i = 0; i < L; i++)
            o = fmaf(wlist[i], vpb[(size_t)tlist[i] * D_], o);
        g_concat[((size_t)b * S_ + s) * D_ + h * 64 + tid] = o / denom;
    }
}

// ---------------- launcher ----------------
extern "C" void kernel_launch(void* const* d_in, const int* in_sizes, int n_in,
                              void* d_out, int out_size) {
    const float* q    = (const float*)d_in[0];
    // d_in[1] = k  (unused in the reference forward)
    const float* v    = (const float*)d_in[2];
    const float* Wv   = (const float*)d_in[3];
    const float* bv   = (const float*)d_in[4];
    const float* W_A  = (const float*)d_in[5];
    const float* W_A2 = (const float*)d_in[6];
    const float* Wo   = (const float*)d_in[7];
    const float* bo   = (const float*)d_in[8];
    float* out = (float*)d_out;

    float* vp;     cudaGetSymbolAddress((void**)&vp,     g_vp);
    float* concat; cudaGetSymbolAddress((void**)&concat, g_concat);

    compute_M_kernel<<<H_, 256>>>(W_A, W_A2);
    qp_kernel<<<B_*S_, 256>>>(q);
    sgemm_nn_bias<<<dim3(D_/128, (B_*S_)/128), 256>>>(B_*S_, D_, D_, v, Wv, bv, vp);
    scores_kernel<<<dim3(S_/128, S_/128, BH_), 256>>>(q);
    softmax_pv_kernel<<<dim3(S_, BH_), 256>>>();
    sgemm_nn_bias<<<dim3(D_/128, (B_*S_)/128), 256>>>(B_*S_, D_, D_, concat, Wo, bo, out);
}